// round 16
// baseline (speedup 1.0000x reference)
#include <cuda_runtime.h>
#include <cstdint>
#include <cstddef>

#define NVEC 1024
#define NDIM 64
#define NHID 32
#define NW   10
#define NB   16
#define NOFF 11

// Scratch (no allocations allowed): device globals.
__device__ float g_w[NW * NB * NOFF * NVEC];   // sparse W values [i][b][o][n]
__device__ float g_H[NW * NB * NVEC * NHID];   // gelu hidden activations (21MB)
__device__ float g_fW2T[NW * NVEC * NHID];     // fW2 transposed [i][n][h]
__device__ float g_fWT3[10 * 16 * NVEC * 4];   // finW as [c][dg][n][4] (2.6MB)
__device__ float g_part[NB * 16 * 10];         // partial sums for output GEMM
__device__ int   g_cnt;                        // block completion counter

// ---------- f32x2 packed helpers (sm_103a FFMA2) ----------
__device__ __forceinline__ unsigned long long pack2(float x, float y) {
    unsigned long long r;
    asm("mov.b64 %0, {%1, %2};" : "=l"(r) : "f"(x), "f"(y));
    return r;
}
__device__ __forceinline__ void fma2(unsigned long long& d, unsigned long long a, unsigned long long b) {
    asm("fma.rn.f32x2 %0, %1, %2, %0;" : "+l"(d) : "l"(a), "l"(b));
}
__device__ __forceinline__ float2 unpack2(unsigned long long v) {
    float lo, hi;
    asm("mov.b64 {%0, %1}, %2;" : "=f"(lo), "=f"(hi) : "l"(v));
    return make_float2(lo, hi);
}
// Fast gelu: A&S 7.1.26 erf approximation, |abs err| <= 1.5e-7 (vs 1e-3 budget).
__device__ __forceinline__ float gelu_exact(float x) {
    float az = fabsf(x) * 0.70710678118f;                 // |x|/sqrt(2)
    float t  = __fdividef(1.0f, fmaf(0.3275911f, az, 1.0f));
    float p  = fmaf(t, 1.061405429f, -1.453152027f);
    p = fmaf(t, p, 1.421413741f);
    p = fmaf(t, p, -0.284496736f);
    p = fmaf(t, p, 0.254829592f);
    p *= t;
    float e = __expf(-az * az);
    float erfz = fmaf(-p, e, 1.0f);                       // erf(|z|)
    float s = copysignf(erfz, x);
    return 0.5f * x * (1.0f + s);
}

// ---------------------------------------------------------------------------
// Kernel A: H = gelu(X @ fW1 + fb1), register-X (no smem X, no mainloop
// barriers), 128 THREADS / 128-row tiles: 64 regs x 128 thr = 8 CTAs/SM ->
// 1184 block slots for 1280 heavy blocks; fine granularity kills the
// 2x wave-quantization penalty (critical path ~= 2 x T_half ~= T_old/2+).
// Per-thread tile unchanged: 4n x 8h. smem = sw1+fb1 only.
// z == 10: transpose fW2 -> g_fW2T.   z == 11: finW -> g_fWT3.
// ---------------------------------------------------------------------------
#define H_SMEM (2816 * 4)   // max(sw1 2080, fW2 tile 1056, sF 2816) floats

__global__ void __launch_bounds__(128, 8) h_kernel(
    const float* __restrict__ data, const float* __restrict__ fW1,
    const float* __restrict__ fb1,  const float* __restrict__ fW2,
    const float* __restrict__ finW)
{
    extern __shared__ float sm[];
    const int t = threadIdx.x;

    // ---------------- fW2 transpose branch (128-thread form) ----------------
    if (blockIdx.z == NW) {
        int idx = blockIdx.y * 8 + blockIdx.x;     // 0..127
        if (idx >= 2 * NW) return;
        const int i  = idx >> 1;
        const int c0 = (idx & 1) * 512;
        float* tile = sm;                          // [32][33]
        for (int s = 0; s < 16; s++) {
#pragma unroll
            for (int it = 0; it < 8; it++) {       // 32x32 tile, 128 threads
                int r = it * 4 + (t >> 5);
                int c = t & 31;
                tile[r * 33 + c] = fW2[((size_t)(i * NHID) + r) * NVEC + c0 + s * 32 + c];
            }
            __syncthreads();
#pragma unroll
            for (int it2 = 0; it2 < 2; it2++) {    // 256 outputs
                int tt = t + 128 * it2;
                int cr = tt >> 3, rg = tt & 7;
                float4 v = make_float4(tile[(4 * rg + 0) * 33 + cr],
                                       tile[(4 * rg + 1) * 33 + cr],
                                       tile[(4 * rg + 2) * 33 + cr],
                                       tile[(4 * rg + 3) * 33 + cr]);
                *reinterpret_cast<float4*>(
                    &g_fW2T[((size_t)(i * NVEC) + c0 + s * 32 + cr) * NHID + 4 * rg]) = v;
            }
            __syncthreads();
        }
        return;
    }

    // ------- finW transpose branch: [f][10] -> [c][dg][n][4] (128-thr) ------
    if (blockIdx.z == NW + 1) {
        int idx = blockIdx.y * 8 + blockIdx.x;     // 0..127
        if (idx >= 32) return;
        float* sF = sm;                            // [256][11]
        float4* dst = reinterpret_cast<float4*>(g_fWT3);
#pragma unroll 1
        for (int s = 0; s < 8; s++) {              // 8 sub-tiles of 256 f
            const int fbase = idx * 2048 + s * 256;
            const int nbase = idx * 32 + s * 4;
            const float4* src =
                reinterpret_cast<const float4*>(finW + (size_t)fbase * 10);
#pragma unroll
            for (int j = 0; j < 5; j++) {          // 640 float4
                int p = t + 128 * j;
                float4 v = __ldg(src + p);
                float vals[4] = {v.x, v.y, v.z, v.w};
#pragma unroll
                for (int u = 0; u < 4; u++) {
                    int e  = 4 * p + u;
                    int fl = e / 10, c = e - 10 * fl;
                    sF[fl * 11 + c] = vals[u];
                }
            }
            __syncthreads();
#pragma unroll
            for (int j = 0; j < 5; j++) {          // 640 outputs
                int oi = t + 128 * j;
                int c  = oi / 64;
                int r  = oi - 64 * c;
                int dg = r >> 2, nn = r & 3;
                float4 v;
                v.x = sF[(nn * 64 + 4 * dg + 0) * 11 + c];
                v.y = sF[(nn * 64 + 4 * dg + 1) * 11 + c];
                v.z = sF[(nn * 64 + 4 * dg + 2) * 11 + c];
                v.w = sF[(nn * 64 + 4 * dg + 3) * 11 + c];
                dst[(c * 16 + dg) * 1024 + nbase + nn] = v;
            }
            __syncthreads();
        }
        return;
    }

    // ---------------- H branch (register-X, 128 rows per block) -------------
    float* sw1  = sm;                   // [64][32]
    float* sfb1 = sw1 + NDIM * NHID;    // [32]

    const int n0 = blockIdx.x * 128;
    const int b  = blockIdx.y;
    const int i  = blockIdx.z;

    for (int idx = t; idx < NDIM * NHID; idx += 128)
        sw1[idx] = fW1[i * NDIM * NHID + idx];
    if (t < NHID) sfb1[t] = fb1[i * NHID + t];

    const int ht8 = (t & 3) * 8;
    const int nb  = (t >> 2) * 4;       // 32 groups x 4 rows = 128 rows

    const float4* r0 = reinterpret_cast<const float4*>(
        data + ((size_t)b * NVEC + n0 + nb + 0) * NDIM);
    const float4* r1 = reinterpret_cast<const float4*>(
        data + ((size_t)b * NVEC + n0 + nb + 1) * NDIM);
    const float4* r2 = reinterpret_cast<const float4*>(
        data + ((size_t)b * NVEC + n0 + nb + 2) * NDIM);
    const float4* r3 = reinterpret_cast<const float4*>(
        data + ((size_t)b * NVEC + n0 + nb + 3) * NDIM);

    unsigned long long acc[4][4];
#pragma unroll
    for (int j = 0; j < 4; j++)
#pragma unroll
        for (int p = 0; p < 4; p++) acc[j][p] = 0ull;

    __syncthreads();   // sw1/sfb1 visible — the ONLY mainloop barrier

#pragma unroll 4
    for (int g = 0; g < 16; g++) {      // 4 k per group
        float4 x0 = __ldg(r0 + g);
        float4 x1 = __ldg(r1 + g);
        float4 x2 = __ldg(r2 + g);
        float4 x3 = __ldg(r3 + g);
        float xr[4][4] = {{x0.x, x0.y, x0.z, x0.w},
                          {x1.x, x1.y, x1.z, x1.w},
                          {x2.x, x2.y, x2.z, x2.w},
                          {x3.x, x3.y, x3.z, x3.w}};
#pragma unroll
        for (int kk = 0; kk < 4; kk++) {
            int k = 4 * g + kk;
            const unsigned long long* wp =
                reinterpret_cast<const unsigned long long*>(&sw1[k * NHID + ht8]);
            unsigned long long w0 = wp[0], w1 = wp[1], w2 = wp[2], w3 = wp[3];
#pragma unroll
            for (int j = 0; j < 4; j++) {
                unsigned long long xx = pack2(xr[j][kk], xr[j][kk]);
                fma2(acc[j][0], xx, w0);
                fma2(acc[j][1], xx, w1);
                fma2(acc[j][2], xx, w2);
                fma2(acc[j][3], xx, w3);
            }
        }
    }

    const unsigned long long* bp =
        reinterpret_cast<const unsigned long long*>(&sfb1[ht8]);
    float2 bb[4];
#pragma unroll
    for (int p = 0; p < 4; p++) bb[p] = unpack2(bp[p]);

    float* Hbase = g_H + ((size_t)(i * NB + b) * NVEC) * NHID;
#pragma unroll
    for (int j = 0; j < 4; j++) {
        float2 v0 = unpack2(acc[j][0]);
        float2 v1 = unpack2(acc[j][1]);
        float2 v2 = unpack2(acc[j][2]);
        float2 v3 = unpack2(acc[j][3]);
        float4 a = make_float4(gelu_exact(v0.x + bb[0].x), gelu_exact(v0.y + bb[0].y),
                               gelu_exact(v1.x + bb[1].x), gelu_exact(v1.y + bb[1].y));
        float4 cc = make_float4(gelu_exact(v2.x + bb[2].x), gelu_exact(v2.y + bb[2].y),
                                gelu_exact(v3.x + bb[3].x), gelu_exact(v3.y + bb[3].y));
        float* dst = Hbase + (size_t)(n0 + nb + j) * NHID + ht8;
        reinterpret_cast<float4*>(dst)[0] = a;
        reinterpret_cast<float4*>(dst)[1] = cc;
    }
}

// ---------------------------------------------------------------------------
// Kernel B (frozen): sparse W values. Block = (b, i), 1024 threads, 160 blocks.
// ---------------------------------------------------------------------------
#define FTS 36
#define W2_SMEM ((NVEC * FTS + NVEC) * 4)   // 151552 B

__global__ void __launch_bounds__(1024) w2_kernel(const float* __restrict__ fb2)
{
    extern __shared__ float sm[];
    float* sfT  = sm;              // [1024][36]
    float* sfb2 = sm + NVEC * FTS; // [1024]

    const int t = threadIdx.x;
    const int b = blockIdx.x;
    const int i = blockIdx.y;

    const float4* src4 =
        reinterpret_cast<const float4*>(g_fW2T + (size_t)i * NVEC * NHID);
#pragma unroll
    for (int q = 0; q < 8; q++) {
        int p = t + 1024 * q;
        float4 v = src4[p];
        int n = p >> 3, c = (p & 7) << 2;
        *reinterpret_cast<float4*>(&sfT[n * FTS + c]) = v;
    }
    sfb2[t] = __ldg(&fb2[i * NVEC + t]);

    float h[32];
    {
        const float4* hp = reinterpret_cast<const float4*>(
            g_H + ((size_t)(i * NB + b) * NVEC + t) * NHID);
#pragma unroll
        for (int q = 0; q < 8; q++) {
            float4 v = __ldg(hp + q);
            h[4 * q] = v.x; h[4 * q + 1] = v.y; h[4 * q + 2] = v.z; h[4 * q + 3] = v.w;
        }
    }
    __syncthreads();

    const int OFF[NOFF] = {0, 1, 2, 4, 8, 16, 32, 64, 128, 256, 512};
    float* out = g_w + (size_t)((i * NB + b) * NOFF) * NVEC + t;
#pragma unroll
    for (int o = 0; o < NOFF; o++) {
        int m = (t + OFF[o]) & (NVEC - 1);
        const float4* rp = reinterpret_cast<const float4*>(&sfT[m * FTS]);
        float s0 = 0.f, s1 = 0.f, s2 = 0.f, s3 = 0.f;
#pragma unroll
        for (int q = 0; q < 8; q++) {
            float4 w = rp[q];
            s0 = fmaf(h[4 * q],     w.x, s0);
            s1 = fmaf(h[4 * q + 1], w.y, s1);
            s2 = fmaf(h[4 * q + 2], w.z, s2);
            s3 = fmaf(h[4 * q + 3], w.w, s3);
        }
        out[(size_t)o * NVEC] = (s0 + s1) + (s2 + s3) + sfb2[m];
    }
}

// ---------------------------------------------------------------------------
// Kernel 2 (frozen): 10-layer sparse recursion, vectorized (block = (dg,b)
// owns 4 dims as float4). 256 blocks, 2 CTAs/SM. Fused output-GEMM epilogue.
// ---------------------------------------------------------------------------
__global__ void __launch_bounds__(1024, 2) recurse_kernel(
    const float* __restrict__ data, const float* __restrict__ finb,
    float* __restrict__ out)
{
    __shared__ float4 Vs[2][NVEC];
    __shared__ int isLast;
    const int t  = threadIdx.x;
    const int dg = blockIdx.x;
    const int b  = blockIdx.y;

    float4 acc = __ldg(reinterpret_cast<const float4*>(
        data + ((size_t)(b * NVEC) + t) * NDIM + 4 * dg));
    Vs[0][t] = acc;

    const int OFF[NOFF] = {0, 1, 2, 4, 8, 16, 32, 64, 128, 256, 512};
    float wv[NOFF];
    {
        const float* w = g_w + (size_t)((9 * NB + b) * NOFF) * NVEC;
#pragma unroll
        for (int o = 0; o < NOFF; o++) wv[o] = __ldg(&w[o * NVEC + t]);
    }
    __syncthreads();

    int cur = 0;
#pragma unroll
    for (int i = NW - 1; i >= 0; i--) {
        float wn[NOFF];
        if (i > 0) {
            const float* w = g_w + (size_t)(((i - 1) * NB + b) * NOFF) * NVEC;
#pragma unroll
            for (int o = 0; o < NOFF; o++) wn[o] = __ldg(&w[o * NVEC + t]);
        }

        float4 na;
        na.x = fmaf(wv[0], acc.x, acc.x);
        na.y = fmaf(wv[0], acc.y, acc.y);
        na.z = fmaf(wv[0], acc.z, acc.z);
        na.w = fmaf(wv[0], acc.w, acc.w);
#pragma unroll
        for (int o = 1; o < NOFF; o++) {
            int m = (t + OFF[o]) & (NVEC - 1);
            float4 v = Vs[cur][m];
            na.x = fmaf(wv[o], v.x, na.x);
            na.y = fmaf(wv[o], v.y, na.y);
            na.z = fmaf(wv[o], v.z, na.z);
            na.w = fmaf(wv[o], v.w, na.w);
        }
        Vs[cur ^ 1][t] = na;
        acc = na;
        __syncthreads();
        cur ^= 1;
#pragma unroll
        for (int o = 0; o < NOFF; o++) wv[o] = wn[o];
    }

    const float4* W3 = reinterpret_cast<const float4*>(g_fWT3);
    float cs[10];
#pragma unroll
    for (int c = 0; c < 10; c++) {
        float4 w = __ldg(&W3[(c * 16 + dg) * 1024 + t]);
        cs[c] = acc.x * w.x + acc.y * w.y + acc.z * w.z + acc.w * w.w;
    }

#pragma unroll
    for (int c = 0; c < 10; c++) {
#pragma unroll
        for (int s = 16; s > 0; s >>= 1)
            cs[c] += __shfl_xor_sync(0xffffffffu, cs[c], s);
    }
    float* red = reinterpret_cast<float*>(&Vs[0][0]);
    int lane = t & 31, wp = t >> 5;
    if (lane == 0) {
#pragma unroll
        for (int c = 0; c < 10; c++) red[wp * 10 + c] = cs[c];
    }
    __syncthreads();
    if (t < 10) {
        float s = 0.f;
        for (int w_ = 0; w_ < 32; w_++) s += red[w_ * 10 + t];
        g_part[(b * 16 + dg) * 10 + t] = s;
    }
    __threadfence();
    if (t == 0) {
        int old = atomicAdd(&g_cnt, 1);
        isLast = (old == NB * 16 - 1);
    }
    __syncthreads();
    if (isLast) {
        __threadfence();
        if (t == 0) g_cnt = 0;
        if (t < NB * 10) {
            int bb = t / 10, c = t - bb * 10;
            float s = __ldg(&finb[c]);
#pragma unroll
            for (int cc = 0; cc < 16; cc++) s += g_part[(bb * 16 + cc) * 10 + c];
            out[t] = s;
        }
    }
}

// ---------------------------------------------------------------------------
extern "C" void kernel_launch(void* const* d_in, const int* in_sizes, int n_in,
                              void* d_out, int out_size)
{
    const float* data = (const float*)d_in[0];
    const float* fW1  = (const float*)d_in[1];
    const float* fb1  = (const float*)d_in[2];
    const float* fW2  = (const float*)d_in[3];
    const float* fb2  = (const float*)d_in[4];
    const float* finW = (const float*)d_in[5];
    const float* finb = (const float*)d_in[6];
    float* out = (float*)d_out;

    cudaFuncSetAttribute(h_kernel,
                         cudaFuncAttributeMaxDynamicSharedMemorySize, H_SMEM);
    cudaFuncSetAttribute(w2_kernel,
                         cudaFuncAttributeMaxDynamicSharedMemorySize, W2_SMEM);

    h_kernel<<<dim3(8, 16, 12), 128, H_SMEM>>>(data, fW1, fb1, fW2, finW);
    w2_kernel<<<dim3(16, 10), 1024, W2_SMEM>>>(fb2);
    recurse_kernel<<<dim3(16, 16), 1024>>>(data, finb, out);
}

// round 17
// speedup vs baseline: 1.0518x; 1.0518x over previous
#include <cuda_runtime.h>
#include <cstdint>
#include <cstddef>

#define NVEC 1024
#define NDIM 64
#define NHID 32
#define NW   10
#define NB   16
#define NOFF 11

// Scratch (no allocations allowed): device globals.
__device__ float g_w[NW * NB * NOFF * NVEC];   // sparse W values [i][b][o][n]
__device__ float g_H[NW * NB * NVEC * NHID];   // gelu hidden activations (21MB)
__device__ float g_fW2T[NW * NVEC * NHID];     // fW2 transposed [i][n][h]
__device__ float g_fWT3[10 * 16 * NVEC * 4];   // finW as [c][dg][n][4] (2.6MB)
__device__ float g_part[NB * 16 * 10];         // partial sums for output GEMM
__device__ int   g_cnt;                        // block completion counter

// ---------- f32x2 packed helpers (sm_103a FFMA2) ----------
__device__ __forceinline__ unsigned long long pack2(float x, float y) {
    unsigned long long r;
    asm("mov.b64 %0, {%1, %2};" : "=l"(r) : "f"(x), "f"(y));
    return r;
}
__device__ __forceinline__ void fma2(unsigned long long& d, unsigned long long a, unsigned long long b) {
    asm("fma.rn.f32x2 %0, %1, %2, %0;" : "+l"(d) : "l"(a), "l"(b));
}
__device__ __forceinline__ float2 unpack2(unsigned long long v) {
    float lo, hi;
    asm("mov.b64 {%0, %1}, %2;" : "=f"(lo), "=f"(hi) : "l"(v));
    return make_float2(lo, hi);
}
// Fast gelu: A&S 7.1.26 erf approximation, |abs err| <= 1.5e-7 (vs 1e-3 budget).
__device__ __forceinline__ float gelu_exact(float x) {
    float az = fabsf(x) * 0.70710678118f;                 // |x|/sqrt(2)
    float t  = __fdividef(1.0f, fmaf(0.3275911f, az, 1.0f));
    float p  = fmaf(t, 1.061405429f, -1.453152027f);
    p = fmaf(t, p, 1.421413741f);
    p = fmaf(t, p, -0.284496736f);
    p = fmaf(t, p, 0.254829592f);
    p *= t;
    float e = __expf(-az * az);
    float erfz = fmaf(-p, e, 1.0f);                       // erf(|z|)
    float s = copysignf(erfz, x);
    return 0.5f * x * (1.0f + s);
}

// ---------------------------------------------------------------------------
// Kernel A: H = gelu(X @ fW1 + fb1), register-X with DOUBLE-BUFFERED register
// prefetch: group g+1's 4 LDG.128 issue BEFORE group g's compute -> per-warp
// MLP=2, hides the ~250cyc L2-hit latency that pinned all prior variants at
// 0.37 IPC. 256 threads, (256,3) -> 85 regs, 24 warps/SM. One barrier total.
// z == 10: transpose fW2 -> g_fW2T.   z == 11: finW -> g_fWT3 (4 sub-tiles).
// ---------------------------------------------------------------------------
#define H_SMEM (2816 * 4)   // max(sw1 2080, fW2 tile 1056, sF 2816) floats

__global__ void __launch_bounds__(256, 3) h_kernel(
    const float* __restrict__ data, const float* __restrict__ fW1,
    const float* __restrict__ fb1,  const float* __restrict__ fW2,
    const float* __restrict__ finW)
{
    extern __shared__ float sm[];
    const int t = threadIdx.x;

    // ---------------- fW2 transpose branch ----------------
    if (blockIdx.z == NW) {
        int idx = blockIdx.y * 4 + blockIdx.x;     // 0..63
        if (idx >= 2 * NW) return;
        const int i  = idx >> 1;
        const int c0 = (idx & 1) * 512;
        float* tile = sm;                          // [32][33]
        for (int s = 0; s < 16; s++) {
#pragma unroll
            for (int it = 0; it < 4; it++) {
                int r = it * 8 + (t >> 5);
                int c = t & 31;
                if (r < 32)
                    tile[r * 33 + c] = fW2[((size_t)(i * NHID) + r) * NVEC + c0 + s * 32 + c];
            }
            __syncthreads();
            int cr = t >> 3, rg = t & 7;
            float4 v = make_float4(tile[(4 * rg + 0) * 33 + cr],
                                   tile[(4 * rg + 1) * 33 + cr],
                                   tile[(4 * rg + 2) * 33 + cr],
                                   tile[(4 * rg + 3) * 33 + cr]);
            *reinterpret_cast<float4*>(
                &g_fW2T[((size_t)(i * NVEC) + c0 + s * 32 + cr) * NHID + 4 * rg]) = v;
            __syncthreads();
        }
        return;
    }

    // ------------- finW transpose branch: [f][10] -> [c][dg][n][4] ----------
    if (blockIdx.z == NW + 1) {
        int idx = blockIdx.y * 4 + blockIdx.x;     // 0..63
        float* sF = sm;                            // [256][11]
        float4* dst = reinterpret_cast<float4*>(g_fWT3);
#pragma unroll 1
        for (int s = 0; s < 4; s++) {
            const int fbase = idx * 1024 + s * 256;
            const int nbase = (idx * 16) + s * 4;
            const float4* src =
                reinterpret_cast<const float4*>(finW + (size_t)fbase * 10);
#pragma unroll
            for (int j = 0; j < 3; j++) {
                int p = t + 256 * j;
                if (p < 640) {
                    float4 v = __ldg(src + p);
                    float vals[4] = {v.x, v.y, v.z, v.w};
#pragma unroll
                    for (int u = 0; u < 4; u++) {
                        int e  = 4 * p + u;
                        int fl = e / 10, c = e - 10 * fl;
                        sF[fl * 11 + c] = vals[u];
                    }
                }
            }
            __syncthreads();
#pragma unroll
            for (int j = 0; j < 3; j++) {
                int oi = t + 256 * j;
                if (oi < 640) {
                    int c  = oi / 64;
                    int r  = oi - 64 * c;
                    int dg = r >> 2, nn = r & 3;
                    float4 v;
                    v.x = sF[(nn * 64 + 4 * dg + 0) * 11 + c];
                    v.y = sF[(nn * 64 + 4 * dg + 1) * 11 + c];
                    v.z = sF[(nn * 64 + 4 * dg + 2) * 11 + c];
                    v.w = sF[(nn * 64 + 4 * dg + 3) * 11 + c];
                    dst[(c * 16 + dg) * 1024 + nbase + nn] = v;
                }
            }
            __syncthreads();
        }
        return;
    }

    // ---------------- H branch (register-X + register prefetch) -------------
    float* sw1  = sm;                   // [64][32]
    float* sfb1 = sw1 + NDIM * NHID;    // [32]

    const int n0 = blockIdx.x * 256;
    const int b  = blockIdx.y;
    const int i  = blockIdx.z;

    for (int idx = t; idx < NDIM * NHID; idx += 256)
        sw1[idx] = fW1[i * NDIM * NHID + idx];
    if (t < NHID) sfb1[t] = fb1[i * NHID + t];

    const int ht8 = (t & 3) * 8;
    const int nb  = (t >> 2) * 4;

    const float4* r0 = reinterpret_cast<const float4*>(
        data + ((size_t)b * NVEC + n0 + nb + 0) * NDIM);
    const float4* r1 = reinterpret_cast<const float4*>(
        data + ((size_t)b * NVEC + n0 + nb + 1) * NDIM);
    const float4* r2 = reinterpret_cast<const float4*>(
        data + ((size_t)b * NVEC + n0 + nb + 2) * NDIM);
    const float4* r3 = reinterpret_cast<const float4*>(
        data + ((size_t)b * NVEC + n0 + nb + 3) * NDIM);

    unsigned long long acc[4][4];
#pragma unroll
    for (int j = 0; j < 4; j++)
#pragma unroll
        for (int p = 0; p < 4; p++) acc[j][p] = 0ull;

    // prologue: group 0 loads in flight
    float4 c0 = __ldg(r0), c1 = __ldg(r1), c2 = __ldg(r2), c3 = __ldg(r3);

    __syncthreads();   // sw1/sfb1 visible — the ONLY mainloop barrier

#pragma unroll 4
    for (int g = 0; g < 16; g++) {
        // prefetch group g+1 BEFORE consuming group g (per-warp MLP = 2)
        float4 p0, p1, p2, p3;
        if (g < 15) {
            p0 = __ldg(r0 + g + 1);
            p1 = __ldg(r1 + g + 1);
            p2 = __ldg(r2 + g + 1);
            p3 = __ldg(r3 + g + 1);
        }

        float xr[4][4] = {{c0.x, c0.y, c0.z, c0.w},
                          {c1.x, c1.y, c1.z, c1.w},
                          {c2.x, c2.y, c2.z, c2.w},
                          {c3.x, c3.y, c3.z, c3.w}};
#pragma unroll
        for (int kk = 0; kk < 4; kk++) {
            int k = 4 * g + kk;
            const unsigned long long* wp =
                reinterpret_cast<const unsigned long long*>(&sw1[k * NHID + ht8]);
            unsigned long long w0 = wp[0], w1 = wp[1], w2 = wp[2], w3 = wp[3];
#pragma unroll
            for (int j = 0; j < 4; j++) {
                unsigned long long xx = pack2(xr[j][kk], xr[j][kk]);
                fma2(acc[j][0], xx, w0);
                fma2(acc[j][1], xx, w1);
                fma2(acc[j][2], xx, w2);
                fma2(acc[j][3], xx, w3);
            }
        }
        c0 = p0; c1 = p1; c2 = p2; c3 = p3;
    }

    const unsigned long long* bp =
        reinterpret_cast<const unsigned long long*>(&sfb1[ht8]);
    float2 bb[4];
#pragma unroll
    for (int p = 0; p < 4; p++) bb[p] = unpack2(bp[p]);

    float* Hbase = g_H + ((size_t)(i * NB + b) * NVEC) * NHID;
#pragma unroll
    for (int j = 0; j < 4; j++) {
        float2 v0 = unpack2(acc[j][0]);
        float2 v1 = unpack2(acc[j][1]);
        float2 v2 = unpack2(acc[j][2]);
        float2 v3 = unpack2(acc[j][3]);
        float4 a = make_float4(gelu_exact(v0.x + bb[0].x), gelu_exact(v0.y + bb[0].y),
                               gelu_exact(v1.x + bb[1].x), gelu_exact(v1.y + bb[1].y));
        float4 cc = make_float4(gelu_exact(v2.x + bb[2].x), gelu_exact(v2.y + bb[2].y),
                                gelu_exact(v3.x + bb[3].x), gelu_exact(v3.y + bb[3].y));
        float* dst = Hbase + (size_t)(n0 + nb + j) * NHID + ht8;
        reinterpret_cast<float4*>(dst)[0] = a;
        reinterpret_cast<float4*>(dst)[1] = cc;
    }
}

// ---------------------------------------------------------------------------
// Kernel B (frozen): sparse W values. Block = (b, i), 1024 threads, 160 blocks.
// ---------------------------------------------------------------------------
#define FTS 36
#define W2_SMEM ((NVEC * FTS + NVEC) * 4)   // 151552 B

__global__ void __launch_bounds__(1024) w2_kernel(const float* __restrict__ fb2)
{
    extern __shared__ float sm[];
    float* sfT  = sm;              // [1024][36]
    float* sfb2 = sm + NVEC * FTS; // [1024]

    const int t = threadIdx.x;
    const int b = blockIdx.x;
    const int i = blockIdx.y;

    const float4* src4 =
        reinterpret_cast<const float4*>(g_fW2T + (size_t)i * NVEC * NHID);
#pragma unroll
    for (int q = 0; q < 8; q++) {
        int p = t + 1024 * q;
        float4 v = src4[p];
        int n = p >> 3, c = (p & 7) << 2;
        *reinterpret_cast<float4*>(&sfT[n * FTS + c]) = v;
    }
    sfb2[t] = __ldg(&fb2[i * NVEC + t]);

    float h[32];
    {
        const float4* hp = reinterpret_cast<const float4*>(
            g_H + ((size_t)(i * NB + b) * NVEC + t) * NHID);
#pragma unroll
        for (int q = 0; q < 8; q++) {
            float4 v = __ldg(hp + q);
            h[4 * q] = v.x; h[4 * q + 1] = v.y; h[4 * q + 2] = v.z; h[4 * q + 3] = v.w;
        }
    }
    __syncthreads();

    const int OFF[NOFF] = {0, 1, 2, 4, 8, 16, 32, 64, 128, 256, 512};
    float* out = g_w + (size_t)((i * NB + b) * NOFF) * NVEC + t;
#pragma unroll
    for (int o = 0; o < NOFF; o++) {
        int m = (t + OFF[o]) & (NVEC - 1);
        const float4* rp = reinterpret_cast<const float4*>(&sfT[m * FTS]);
        float s0 = 0.f, s1 = 0.f, s2 = 0.f, s3 = 0.f;
#pragma unroll
        for (int q = 0; q < 8; q++) {
            float4 w = rp[q];
            s0 = fmaf(h[4 * q],     w.x, s0);
            s1 = fmaf(h[4 * q + 1], w.y, s1);
            s2 = fmaf(h[4 * q + 2], w.z, s2);
            s3 = fmaf(h[4 * q + 3], w.w, s3);
        }
        out[(size_t)o * NVEC] = (s0 + s1) + (s2 + s3) + sfb2[m];
    }
}

// ---------------------------------------------------------------------------
// Kernel 2 (frozen): 10-layer sparse recursion, vectorized (block = (dg,b)
// owns 4 dims as float4). 256 blocks, 2 CTAs/SM. Fused output-GEMM epilogue.
// ---------------------------------------------------------------------------
__global__ void __launch_bounds__(1024, 2) recurse_kernel(
    const float* __restrict__ data, const float* __restrict__ finb,
    float* __restrict__ out)
{
    __shared__ float4 Vs[2][NVEC];
    __shared__ int isLast;
    const int t  = threadIdx.x;
    const int dg = blockIdx.x;
    const int b  = blockIdx.y;

    float4 acc = __ldg(reinterpret_cast<const float4*>(
        data + ((size_t)(b * NVEC) + t) * NDIM + 4 * dg));
    Vs[0][t] = acc;

    const int OFF[NOFF] = {0, 1, 2, 4, 8, 16, 32, 64, 128, 256, 512};
    float wv[NOFF];
    {
        const float* w = g_w + (size_t)((9 * NB + b) * NOFF) * NVEC;
#pragma unroll
        for (int o = 0; o < NOFF; o++) wv[o] = __ldg(&w[o * NVEC + t]);
    }
    __syncthreads();

    int cur = 0;
#pragma unroll
    for (int i = NW - 1; i >= 0; i--) {
        float wn[NOFF];
        if (i > 0) {
            const float* w = g_w + (size_t)(((i - 1) * NB + b) * NOFF) * NVEC;
#pragma unroll
            for (int o = 0; o < NOFF; o++) wn[o] = __ldg(&w[o * NVEC + t]);
        }

        float4 na;
        na.x = fmaf(wv[0], acc.x, acc.x);
        na.y = fmaf(wv[0], acc.y, acc.y);
        na.z = fmaf(wv[0], acc.z, acc.z);
        na.w = fmaf(wv[0], acc.w, acc.w);
#pragma unroll
        for (int o = 1; o < NOFF; o++) {
            int m = (t + OFF[o]) & (NVEC - 1);
            float4 v = Vs[cur][m];
            na.x = fmaf(wv[o], v.x, na.x);
            na.y = fmaf(wv[o], v.y, na.y);
            na.z = fmaf(wv[o], v.z, na.z);
            na.w = fmaf(wv[o], v.w, na.w);
        }
        Vs[cur ^ 1][t] = na;
        acc = na;
        __syncthreads();
        cur ^= 1;
#pragma unroll
        for (int o = 0; o < NOFF; o++) wv[o] = wn[o];
    }

    const float4* W3 = reinterpret_cast<const float4*>(g_fWT3);
    float cs[10];
#pragma unroll
    for (int c = 0; c < 10; c++) {
        float4 w = __ldg(&W3[(c * 16 + dg) * 1024 + t]);
        cs[c] = acc.x * w.x + acc.y * w.y + acc.z * w.z + acc.w * w.w;
    }

#pragma unroll
    for (int c = 0; c < 10; c++) {
#pragma unroll
        for (int s = 16; s > 0; s >>= 1)
            cs[c] += __shfl_xor_sync(0xffffffffu, cs[c], s);
    }
    float* red = reinterpret_cast<float*>(&Vs[0][0]);
    int lane = t & 31, wp = t >> 5;
    if (lane == 0) {
#pragma unroll
        for (int c = 0; c < 10; c++) red[wp * 10 + c] = cs[c];
    }
    __syncthreads();
    if (t < 10) {
        float s = 0.f;
        for (int w_ = 0; w_ < 32; w_++) s += red[w_ * 10 + t];
        g_part[(b * 16 + dg) * 10 + t] = s;
    }
    __threadfence();
    if (t == 0) {
        int old = atomicAdd(&g_cnt, 1);
        isLast = (old == NB * 16 - 1);
    }
    __syncthreads();
    if (isLast) {
        __threadfence();
        if (t == 0) g_cnt = 0;
        if (t < NB * 10) {
            int bb = t / 10, c = t - bb * 10;
            float s = __ldg(&finb[c]);
#pragma unroll
            for (int cc = 0; cc < 16; cc++) s += g_part[(bb * 16 + cc) * 10 + c];
            out[t] = s;
        }
    }
}

// ---------------------------------------------------------------------------
extern "C" void kernel_launch(void* const* d_in, const int* in_sizes, int n_in,
                              void* d_out, int out_size)
{
    const float* data = (const float*)d_in[0];
    const float* fW1  = (const float*)d_in[1];
    const float* fb1  = (const float*)d_in[2];
    const float* fW2  = (const float*)d_in[3];
    const float* fb2  = (const float*)d_in[4];
    const float* finW = (const float*)d_in[5];
    const float* finb = (const float*)d_in[6];
    float* out = (float*)d_out;

    cudaFuncSetAttribute(h_kernel,
                         cudaFuncAttributeMaxDynamicSharedMemorySize, H_SMEM);
    cudaFuncSetAttribute(w2_kernel,
                         cudaFuncAttributeMaxDynamicSharedMemorySize, W2_SMEM);

    h_kernel<<<dim3(4, 16, 12), 256, H_SMEM>>>(data, fW1, fb1, fW2, finW);
    w2_kernel<<<dim3(16, 10), 1024, W2_SMEM>>>(fb2);
    recurse_kernel<<<dim3(16, 16), 1024>>>(data, finb, out);
}